// round 4
// baseline (speedup 1.0000x reference)
#include <cuda_runtime.h>

#define N 4096
#define D 256
#define C 1000
#define BM 64
#define BK 32

// Global scratch (no allocations allowed in kernel_launch).
__device__ double g_acc[4];        // [0]=label sumsq, [1..3]=feature sumsq
__device__ float  g_sqn[6][N];     // row squared norms: 0..2 = pred_f, 3..5 = target_f

// ---------------------------------------------------------------------------
__global__ void zero_kernel() {
    if (threadIdx.x < 4) g_acc[threadIdx.x] = 0.0;
}

// ---------------------------------------------------------------------------
// Row squared norms for all 6 feature matrices. One warp per row.
__global__ void sqn_kernel(const float* __restrict__ f0, const float* __restrict__ f1,
                           const float* __restrict__ f2, const float* __restrict__ f3,
                           const float* __restrict__ f4, const float* __restrict__ f5) {
    int gw   = (blockIdx.x * blockDim.x + threadIdx.x) >> 5;
    int lane = threadIdx.x & 31;
    if (gw >= 6 * N) return;
    int f = gw >> 12;          // /4096
    int row = gw & (N - 1);
    const float* src;
    switch (f) {
        case 0: src = f0; break; case 1: src = f1; break; case 2: src = f2; break;
        case 3: src = f3; break; case 4: src = f4; break; default: src = f5; break;
    }
    const float4* p = (const float4*)(src + (size_t)row * D);
    float s = 0.f;
#pragma unroll
    for (int i = 0; i < 2; i++) {
        float4 v = p[lane + 32 * i];
        s += v.x * v.x + v.y * v.y + v.z * v.z + v.w * v.w;
    }
#pragma unroll
    for (int o = 16; o; o >>= 1) s += __shfl_xor_sync(0xffffffffu, s, o);
    if (lane == 0) g_sqn[f][row] = s;
}

// ---------------------------------------------------------------------------
// Label MSE sum: sum((pred - target)^2) over N*C elements.
__global__ void label_kernel(const float* __restrict__ pred,
                             const float* __restrict__ target) {
    __shared__ float sred[256];
    const int n4 = N * C / 4;
    float s = 0.f;
    for (int i = blockIdx.x * blockDim.x + threadIdx.x; i < n4;
         i += gridDim.x * blockDim.x) {
        float4 a = ((const float4*)pred)[i];
        float4 b = ((const float4*)target)[i];
        float dx = a.x - b.x, dy = a.y - b.y, dz = a.z - b.z, dw = a.w - b.w;
        s += dx * dx + dy * dy + dz * dz + dw * dw;
    }
    sred[threadIdx.x] = s;
    __syncthreads();
    for (int o = 128; o; o >>= 1) {
        if (threadIdx.x < o) sred[threadIdx.x] += sred[threadIdx.x + o];
        __syncthreads();
    }
    if (threadIdx.x == 0) atomicAdd(&g_acc[0], (double)sred[0]);
}

// ---------------------------------------------------------------------------
// Fused pairwise kernel: for one 64x64 tile of the NxN distance matrices,
// compute dotP = Pi·Pj and dotT = Ti·Tj (two SGEMM micro-tiles), then
// d = sqrt(max(sqn_i + sqn_j - 2*dot, 0)) for each, accumulate (dP - dT)^2.
// Only upper-triangular tiles are computed (symmetry), off-diag weighted x2.
__global__ void __launch_bounds__(256)
pair_kernel(const float* __restrict__ pf0, const float* __restrict__ pf1,
            const float* __restrict__ pf2, const float* __restrict__ tf0,
            const float* __restrict__ tf1, const float* __restrict__ tf2) {
    int bj = blockIdx.x, bi = blockIdx.y, f = blockIdx.z;
    if (bj < bi) return;

    const float *P, *T;
    if (f == 0)      { P = pf0; T = tf0; }
    else if (f == 1) { P = pf1; T = tf1; }
    else             { P = pf2; T = tf2; }

    __shared__ float sPi[BM][BK + 1], sPj[BM][BK + 1];
    __shared__ float sTi[BM][BK + 1], sTj[BM][BK + 1];
    __shared__ float sred[256];

    const int tx = threadIdx.x, ty = threadIdx.y;   // 16x16
    const int tid = ty * 16 + tx;
    const int rowI = bi * BM, rowJ = bj * BM;

    float accP[4][4] = {}, accT[4][4] = {};

    for (int k0 = 0; k0 < D; k0 += BK) {
        // Load 4 tiles of 64x32 floats. 512 float4 per tile; 2 per thread.
#pragma unroll
        for (int l = tid; l < (BM * BK / 4); l += 256) {
            int m  = l >> 3;
            int kk = (l & 7) << 2;
            float4 v;
            v = *(const float4*)&P[(size_t)(rowI + m) * D + k0 + kk];
            sPi[m][kk] = v.x; sPi[m][kk + 1] = v.y; sPi[m][kk + 2] = v.z; sPi[m][kk + 3] = v.w;
            v = *(const float4*)&P[(size_t)(rowJ + m) * D + k0 + kk];
            sPj[m][kk] = v.x; sPj[m][kk + 1] = v.y; sPj[m][kk + 2] = v.z; sPj[m][kk + 3] = v.w;
            v = *(const float4*)&T[(size_t)(rowI + m) * D + k0 + kk];
            sTi[m][kk] = v.x; sTi[m][kk + 1] = v.y; sTi[m][kk + 2] = v.z; sTi[m][kk + 3] = v.w;
            v = *(const float4*)&T[(size_t)(rowJ + m) * D + k0 + kk];
            sTj[m][kk] = v.x; sTj[m][kk + 1] = v.y; sTj[m][kk + 2] = v.z; sTj[m][kk + 3] = v.w;
        }
        __syncthreads();

#pragma unroll
        for (int k = 0; k < BK; k++) {
            float aP[4], bP[4], aT[4], bT[4];
#pragma unroll
            for (int r = 0; r < 4; r++) {
                aP[r] = sPi[ty * 4 + r][k];
                aT[r] = sTi[ty * 4 + r][k];
                bP[r] = sPj[tx * 4 + r][k];
                bT[r] = sTj[tx * 4 + r][k];
            }
#pragma unroll
            for (int r = 0; r < 4; r++)
#pragma unroll
                for (int c = 0; c < 4; c++) {
                    accP[r][c] += aP[r] * bP[c];
                    accT[r][c] += aT[r] * bT[c];
                }
        }
        __syncthreads();
    }

    // Epilogue: distances, diff^2, tile reduction.
    const float w = (bi == bj) ? 1.0f : 2.0f;
    float s = 0.f;
#pragma unroll
    for (int r = 0; r < 4; r++) {
        int i = rowI + ty * 4 + r;
        float sqPi = g_sqn[f][i];
        float sqTi = g_sqn[3 + f][i];
#pragma unroll
        for (int c = 0; c < 4; c++) {
            int j = rowJ + tx * 4 + c;
            float sp = sqPi + g_sqn[f][j]     - 2.f * accP[r][c];
            float st = sqTi + g_sqn[3 + f][j] - 2.f * accT[r][c];
            float dp = sp > 0.f ? sqrtf(sp) : 0.f;
            float dt = st > 0.f ? sqrtf(st) : 0.f;
            float d = dp - dt;
            s += d * d;
        }
    }
    sred[tid] = s * w;
    __syncthreads();
    for (int o = 128; o; o >>= 1) {
        if (tid < o) sred[tid] += sred[tid + o];
        __syncthreads();
    }
    if (tid == 0) atomicAdd(&g_acc[1 + f], (double)sred[0]);
}

// ---------------------------------------------------------------------------
__global__ void final_kernel(float* __restrict__ out) {
    double label = g_acc[0] / ((double)N * (double)C);
    double feat  = (g_acc[1] + g_acc[2] + g_acc[3]) / ((double)N * (double)N);
    out[0] = (float)((1.0 - 0.8) * label + 0.8 * feat / 3.0);
}

// ---------------------------------------------------------------------------
extern "C" void kernel_launch(void* const* d_in, const int* in_sizes, int n_in,
                              void* d_out, int out_size) {
    const float* pred   = (const float*)d_in[0];
    const float* target = (const float*)d_in[1];
    const float* pf0 = (const float*)d_in[2];
    const float* pf1 = (const float*)d_in[3];
    const float* pf2 = (const float*)d_in[4];
    const float* tf0 = (const float*)d_in[5];
    const float* tf1 = (const float*)d_in[6];
    const float* tf2 = (const float*)d_in[7];
    float* out = (float*)d_out;

    zero_kernel<<<1, 32>>>();

    // Row squared norms: 6*4096 rows, one warp each, 8 rows per 256-thread block.
    sqn_kernel<<<(6 * N) / 8, 256>>>(pf0, pf1, pf2, tf0, tf1, tf2);

    label_kernel<<<512, 256>>>(pred, target);

    dim3 grid(N / BM, N / BM, 3);   // 64 x 64 x 3; lower-tri blocks exit early
    dim3 block(16, 16);
    pair_kernel<<<grid, block>>>(pf0, pf1, pf2, tf0, tf1, tf2);

    final_kernel<<<1, 1>>>(out);
}

// round 5
// speedup vs baseline: 1.5919x; 1.5919x over previous
#include <cuda_runtime.h>

#define N 4096
#define D 256
#define C 1000
#define BM 128
#define BK 16
#define NT (N / BM)                 // 32 tile-rows
#define NTILES (NT * (NT + 1) / 2)  // 528 upper-tri tiles
#define PITCH 132                   // BM + 4 pad (keeps float4 alignment, kills LDS conflicts)

// Global scratch (no allocations allowed).
__device__ double g_acc[4];     // [0]=label sumsq, [1..3]=feature sumsq
__device__ float  g_sqn[6][N];  // row squared norms: 0..2 pred_f, 3..5 target_f

// ---------------------------------------------------------------------------
__global__ void zero_kernel() {
    if (threadIdx.x < 4) g_acc[threadIdx.x] = 0.0;
}

// ---------------------------------------------------------------------------
// Row squared norms for all 6 feature matrices. One warp per row.
__global__ void sqn_kernel(const float* __restrict__ f0, const float* __restrict__ f1,
                           const float* __restrict__ f2, const float* __restrict__ f3,
                           const float* __restrict__ f4, const float* __restrict__ f5) {
    int gw   = (blockIdx.x * blockDim.x + threadIdx.x) >> 5;
    int lane = threadIdx.x & 31;
    if (gw >= 6 * N) return;
    int f = gw >> 12;
    int row = gw & (N - 1);
    const float* src;
    switch (f) {
        case 0: src = f0; break; case 1: src = f1; break; case 2: src = f2; break;
        case 3: src = f3; break; case 4: src = f4; break; default: src = f5; break;
    }
    const float4* p = (const float4*)(src + (size_t)row * D);
    float s = 0.f;
#pragma unroll
    for (int i = 0; i < 2; i++) {
        float4 v = p[lane + 32 * i];
        s += v.x * v.x + v.y * v.y + v.z * v.z + v.w * v.w;
    }
#pragma unroll
    for (int o = 16; o; o >>= 1) s += __shfl_xor_sync(0xffffffffu, s, o);
    if (lane == 0) g_sqn[f][row] = s;
}

// ---------------------------------------------------------------------------
__global__ void label_kernel(const float* __restrict__ pred,
                             const float* __restrict__ target) {
    __shared__ float sred[256];
    const int n4 = N * C / 4;
    float s = 0.f;
    for (int i = blockIdx.x * blockDim.x + threadIdx.x; i < n4;
         i += gridDim.x * blockDim.x) {
        float4 a = ((const float4*)pred)[i];
        float4 b = ((const float4*)target)[i];
        float dx = a.x - b.x, dy = a.y - b.y, dz = a.z - b.z, dw = a.w - b.w;
        s += dx * dx + dy * dy + dz * dz + dw * dw;
    }
    sred[threadIdx.x] = s;
    __syncthreads();
    for (int o = 128; o; o >>= 1) {
        if (threadIdx.x < o) sred[threadIdx.x] += sred[threadIdx.x + o];
        __syncthreads();
    }
    if (threadIdx.x == 0) atomicAdd(&g_acc[0], (double)sred[0]);
}

// ---------------------------------------------------------------------------
// Fused pairwise kernel. One 128x128 upper-triangular tile of the NxN distance
// matrices per block. Two sequential SGEMM phases (P then T) with an 8x8
// micro-tile per thread; dP is parked in thread-private shared memory between
// the phases. Double-buffered smem tiles, register prefetch of the next chunk.
__global__ void __launch_bounds__(256, 2)
pair_kernel(const float* __restrict__ pf0, const float* __restrict__ pf1,
            const float* __restrict__ pf2, const float* __restrict__ tf0,
            const float* __restrict__ tf1, const float* __restrict__ tf2) {
    extern __shared__ float sm[];
    // Layout: [buf0 A | buf0 B | buf1 A | buf1 B] each BK*PITCH floats,
    // then sdP (64 * 256 floats, thread-private), then sred (8 floats).
    float* sdP  = sm + 4 * BK * PITCH;
    float* sred = sdP + 64 * 256;

    const int f = blockIdx.y;
    // Decode linear index -> upper-triangular (bi, bj), bj >= bi.
    int bi = 0, rem = blockIdx.x;
    while (rem >= NT - bi) { rem -= NT - bi; bi++; }
    const int bj = bi + rem;

    const float *P, *T;
    if (f == 0)      { P = pf0; T = tf0; }
    else if (f == 1) { P = pf1; T = tf1; }
    else             { P = pf2; T = tf2; }

    const int tid = threadIdx.x;
    const int tx = tid & 15, ty = tid >> 4;          // 16 x 16
    const int rowI = bi * BM, rowJ = bj * BM;

    // Per-thread load slots: A needs 512 float4 per chunk, B likewise -> 2 each.
    const int m0 = tid >> 2;                 // 0..63
    const int m1 = (tid + 256) >> 2;         // 64..127
    const int kq0 = (tid & 3) << 2;          // k sub-offset 0/4/8/12
    const int kq1 = kq0;                     // (tid+256)&3 == tid&3

    float s = 0.f;

#pragma unroll 1
    for (int phase = 0; phase < 2; ++phase) {
        const float* F  = phase ? T : P;
        const float* Ag = F + (size_t)rowI * D;
        const float* Bg = F + (size_t)rowJ * D;

        float acc[8][8];
#pragma unroll
        for (int r = 0; r < 8; r++)
#pragma unroll
            for (int c = 0; c < 8; c++) acc[r][c] = 0.f;

        // Prefetch chunk 0 into registers.
        float4 ra0 = *(const float4*)&Ag[m0 * D + kq0];
        float4 ra1 = *(const float4*)&Ag[m1 * D + kq1];
        float4 rb0 = *(const float4*)&Bg[m0 * D + kq0];
        float4 rb1 = *(const float4*)&Bg[m1 * D + kq1];

        // Store chunk 0 to buffer 0.
        {
            float* sA = sm;
            float* sB = sm + BK * PITCH;
            sA[(kq0 + 0) * PITCH + m0] = ra0.x; sA[(kq0 + 1) * PITCH + m0] = ra0.y;
            sA[(kq0 + 2) * PITCH + m0] = ra0.z; sA[(kq0 + 3) * PITCH + m0] = ra0.w;
            sA[(kq1 + 0) * PITCH + m1] = ra1.x; sA[(kq1 + 1) * PITCH + m1] = ra1.y;
            sA[(kq1 + 2) * PITCH + m1] = ra1.z; sA[(kq1 + 3) * PITCH + m1] = ra1.w;
            sB[(kq0 + 0) * PITCH + m0] = rb0.x; sB[(kq0 + 1) * PITCH + m0] = rb0.y;
            sB[(kq0 + 2) * PITCH + m0] = rb0.z; sB[(kq0 + 3) * PITCH + m0] = rb0.w;
            sB[(kq1 + 0) * PITCH + m1] = rb1.x; sB[(kq1 + 1) * PITCH + m1] = rb1.y;
            sB[(kq1 + 2) * PITCH + m1] = rb1.z; sB[(kq1 + 3) * PITCH + m1] = rb1.w;
        }
        __syncthreads();

        int buf = 0;
#pragma unroll 1
        for (int kc = 0; kc < D / BK; kc++) {
            // Prefetch next chunk from global (L2-resident).
            if (kc < D / BK - 1) {
                const int k0 = (kc + 1) * BK;
                ra0 = *(const float4*)&Ag[m0 * D + k0 + kq0];
                ra1 = *(const float4*)&Ag[m1 * D + k0 + kq1];
                rb0 = *(const float4*)&Bg[m0 * D + k0 + kq0];
                rb1 = *(const float4*)&Bg[m1 * D + k0 + kq1];
            }

            // Compute on current buffer.
            const float* sA = sm + (buf * 2) * BK * PITCH;
            const float* sB = sA + BK * PITCH;
#pragma unroll
            for (int k = 0; k < BK; k++) {
                float4 a0 = *(const float4*)&sA[k * PITCH + 8 * ty];
                float4 a1 = *(const float4*)&sA[k * PITCH + 8 * ty + 4];
                float4 b0 = *(const float4*)&sB[k * PITCH + 8 * tx];
                float4 b1 = *(const float4*)&sB[k * PITCH + 8 * tx + 4];
                float a[8] = {a0.x, a0.y, a0.z, a0.w, a1.x, a1.y, a1.z, a1.w};
                float b[8] = {b0.x, b0.y, b0.z, b0.w, b1.x, b1.y, b1.z, b1.w};
#pragma unroll
                for (int r = 0; r < 8; r++)
#pragma unroll
                    for (int c = 0; c < 8; c++)
                        acc[r][c] += a[r] * b[c];
            }

            if (kc < D / BK - 1) {
                // Write next chunk to the other buffer (safe: all threads are
                // past the sync that ended the previous iteration).
                float* dA = sm + ((buf ^ 1) * 2) * BK * PITCH;
                float* dB = dA + BK * PITCH;
                dA[(kq0 + 0) * PITCH + m0] = ra0.x; dA[(kq0 + 1) * PITCH + m0] = ra0.y;
                dA[(kq0 + 2) * PITCH + m0] = ra0.z; dA[(kq0 + 3) * PITCH + m0] = ra0.w;
                dA[(kq1 + 0) * PITCH + m1] = ra1.x; dA[(kq1 + 1) * PITCH + m1] = ra1.y;
                dA[(kq1 + 2) * PITCH + m1] = ra1.z; dA[(kq1 + 3) * PITCH + m1] = ra1.w;
                dB[(kq0 + 0) * PITCH + m0] = rb0.x; dB[(kq0 + 1) * PITCH + m0] = rb0.y;
                dB[(kq0 + 2) * PITCH + m0] = rb0.z; dB[(kq0 + 3) * PITCH + m0] = rb0.w;
                dB[(kq1 + 0) * PITCH + m1] = rb1.x; dB[(kq1 + 1) * PITCH + m1] = rb1.y;
                dB[(kq1 + 2) * PITCH + m1] = rb1.z; dB[(kq1 + 3) * PITCH + m1] = rb1.w;
                __syncthreads();
                buf ^= 1;
            }
        }

        // Epilogue. sdP slots are thread-private -> no sync needed around them.
        if (phase == 0) {
#pragma unroll
            for (int r = 0; r < 8; r++) {
                float sqi = g_sqn[f][rowI + 8 * ty + r];
#pragma unroll
                for (int c = 0; c < 8; c++) {
                    float sq = sqi + g_sqn[f][rowJ + 8 * tx + c] - 2.f * acc[r][c];
                    float dp = sq > 0.f ? sq * rsqrtf(sq) : 0.f;
                    sdP[(r * 8 + c) * 256 + tid] = dp;
                }
            }
        } else {
#pragma unroll
            for (int r = 0; r < 8; r++) {
                float sqi = g_sqn[3 + f][rowI + 8 * ty + r];
#pragma unroll
                for (int c = 0; c < 8; c++) {
                    float sq = sqi + g_sqn[3 + f][rowJ + 8 * tx + c] - 2.f * acc[r][c];
                    float dt = sq > 0.f ? sq * rsqrtf(sq) : 0.f;
                    float d = sdP[(r * 8 + c) * 256 + tid] - dt;
                    s += d * d;
                }
            }
        }
    }

    // Reduce: off-diagonal tiles counted twice (symmetry).
    s *= (bi == bj) ? 1.f : 2.f;
#pragma unroll
    for (int o = 16; o; o >>= 1) s += __shfl_xor_sync(0xffffffffu, s, o);
    if ((tid & 31) == 0) sred[tid >> 5] = s;
    __syncthreads();
    if (tid == 0) {
        double tot = 0.0;
#pragma unroll
        for (int w = 0; w < 8; w++) tot += (double)sred[w];
        atomicAdd(&g_acc[1 + f], tot);
    }
}

// ---------------------------------------------------------------------------
__global__ void final_kernel(float* __restrict__ out) {
    double label = g_acc[0] / ((double)N * (double)C);
    double feat  = (g_acc[1] + g_acc[2] + g_acc[3]) / ((double)N * (double)N);
    out[0] = (float)((1.0 - 0.8) * label + 0.8 * feat / 3.0);
}

// ---------------------------------------------------------------------------
extern "C" void kernel_launch(void* const* d_in, const int* in_sizes, int n_in,
                              void* d_out, int out_size) {
    const float* pred   = (const float*)d_in[0];
    const float* target = (const float*)d_in[1];
    const float* pf0 = (const float*)d_in[2];
    const float* pf1 = (const float*)d_in[3];
    const float* pf2 = (const float*)d_in[4];
    const float* tf0 = (const float*)d_in[5];
    const float* tf1 = (const float*)d_in[6];
    const float* tf2 = (const float*)d_in[7];
    float* out = (float*)d_out;

    static int smem_configured = 0;
    const size_t smemB = (4 * BK * PITCH + 64 * 256 + 8) * sizeof(float);
    if (!smem_configured) {
        cudaFuncSetAttribute(pair_kernel,
                             cudaFuncAttributeMaxDynamicSharedMemorySize,
                             (int)smemB);
        smem_configured = 1;
    }

    zero_kernel<<<1, 32>>>();
    sqn_kernel<<<(6 * N) / 8, 256>>>(pf0, pf1, pf2, tf0, tf1, tf2);
    label_kernel<<<512, 256>>>(pred, target);

    dim3 grid(NTILES, 3);
    pair_kernel<<<grid, 256, smemB>>>(pf0, pf1, pf2, tf0, tf1, tf2);

    final_kernel<<<1, 1>>>(out);
}

// round 7
// speedup vs baseline: 2.9346x; 1.8434x over previous
#include <cuda_runtime.h>
#include <cstdint>

#define N 4096
#define D 256
#define C 1000
#define BM 128
#define NT (N / BM)                 // 32
#define NTILES (NT * (NT + 1) / 2)  // 528
#define BK 16
#define PITCH 24                    // floats per tile row (16 slots + pad)
#define TILE_F (BM * PITCH)         // 3072 floats per operand tile

// Shared memory layout (floats):
#define OFF_SDP   0                       // 64*256 = 16384 (parked dP)
#define OFF_TILES 16384                   // 4 tiles (2 stages x {A,B}) = 12288
#define OFF_SQ    (OFF_TILES + 4 * TILE_F)// sqIP,sqJP,sqIT,sqJT = 512
#define OFF_SRED  (OFF_SQ + 512)          // 8
#define SMEM_FLOATS (OFF_SRED + 8)
#define SMEM_BYTES (SMEM_FLOATS * 4)      // 116768 B

__device__ double g_acc[4];
__device__ float  g_sqn[6][N];

// ---------------------------------------------------------------------------
__device__ __forceinline__ uint32_t to_tf32(float f) {
    uint32_t u;
    asm("cvt.rna.tf32.f32 %0, %1;" : "=r"(u) : "f"(f));
    return u;
}

__device__ __forceinline__ void mma_tf32(float* d, uint32_t a0, uint32_t a1,
                                         uint32_t a2, uint32_t a3,
                                         uint32_t b0, uint32_t b1) {
    asm volatile(
        "mma.sync.aligned.m16n8k8.row.col.f32.tf32.tf32.f32 "
        "{%0,%1,%2,%3}, {%4,%5,%6,%7}, {%8,%9}, {%0,%1,%2,%3};"
        : "+f"(d[0]), "+f"(d[1]), "+f"(d[2]), "+f"(d[3])
        : "r"(a0), "r"(a1), "r"(a2), "r"(a3), "r"(b0), "r"(b1));
}

// ---------------------------------------------------------------------------
__global__ void zero_kernel() {
    if (threadIdx.x < 4) g_acc[threadIdx.x] = 0.0;
}

// Row squared norms, one warp per row. fp32 (full precision).
__global__ void sqn_kernel(const float* __restrict__ f0, const float* __restrict__ f1,
                           const float* __restrict__ f2, const float* __restrict__ f3,
                           const float* __restrict__ f4, const float* __restrict__ f5) {
    int gw   = (blockIdx.x * blockDim.x + threadIdx.x) >> 5;
    int lane = threadIdx.x & 31;
    if (gw >= 6 * N) return;
    int f = gw >> 12;
    int row = gw & (N - 1);
    const float* src;
    switch (f) {
        case 0: src = f0; break; case 1: src = f1; break; case 2: src = f2; break;
        case 3: src = f3; break; case 4: src = f4; break; default: src = f5; break;
    }
    const float4* p = (const float4*)(src + (size_t)row * D);
    float s = 0.f;
#pragma unroll
    for (int i = 0; i < 2; i++) {
        float4 v = p[lane + 32 * i];
        s += v.x * v.x + v.y * v.y + v.z * v.z + v.w * v.w;
    }
#pragma unroll
    for (int o = 16; o; o >>= 1) s += __shfl_xor_sync(0xffffffffu, s, o);
    if (lane == 0) g_sqn[f][row] = s;
}

__global__ void label_kernel(const float* __restrict__ pred,
                             const float* __restrict__ target) {
    __shared__ float sred[256];
    const int n4 = N * C / 4;
    float s = 0.f;
    for (int i = blockIdx.x * blockDim.x + threadIdx.x; i < n4;
         i += gridDim.x * blockDim.x) {
        float4 a = ((const float4*)pred)[i];
        float4 b = ((const float4*)target)[i];
        float dx = a.x - b.x, dy = a.y - b.y, dz = a.z - b.z, dw = a.w - b.w;
        s += dx * dx + dy * dy + dz * dz + dw * dw;
    }
    sred[threadIdx.x] = s;
    __syncthreads();
    for (int o = 128; o; o >>= 1) {
        if (threadIdx.x < o) sred[threadIdx.x] += sred[threadIdx.x + o];
        __syncthreads();
    }
    if (threadIdx.x == 0) atomicAdd(&g_acc[0], (double)sred[0]);
}

// ---------------------------------------------------------------------------
// Tensor-core (mma.sync tf32) fused pairwise tile kernel.
// One 128x128 upper-tri tile per block; 8 warps (4 row-groups x 2 col-groups),
// warp tile 32x64. Phase 0: Gram(P) -> distances parked in smem. Phase 1:
// Gram(T) -> accumulate (dP - dT)^2.
//
// Smem tile layout: [row][slot] with PITCH=24, BK=16 split into two k8 groups;
// within a group, k -> slot 2*(k%4) + (k>=4), so every MMA fragment pair is
// one conflict-free LDS.64.
__global__ void __launch_bounds__(256, 1)
pair_kernel(const float* __restrict__ pf0, const float* __restrict__ pf1,
            const float* __restrict__ pf2, const float* __restrict__ tf0,
            const float* __restrict__ tf1, const float* __restrict__ tf2) {
    extern __shared__ float sm[];

    const int f = blockIdx.y;
    int bi = 0, rem = blockIdx.x;
    while (rem >= NT - bi) { rem -= NT - bi; bi++; }
    const int bj = bi + rem;

    const float *P, *T;
    if (f == 0)      { P = pf0; T = tf0; }
    else if (f == 1) { P = pf1; T = tf1; }
    else             { P = pf2; T = tf2; }

    const int tid  = threadIdx.x;
    const int wid  = tid >> 5, lane = tid & 31;
    const int wi   = wid & 3;        // row warp group: rows wi*32..+32
    const int wj   = wid >> 2;       // col warp group: cols wj*64..+64
    const int tg   = lane >> 2;      // 0..7 (fragment group/row)
    const int q    = lane & 3;       // 0..3 (fragment quad)
    const int rowI = bi * BM, rowJ = bj * BM;

    // Stage squared norms.
    if (tid < 128) {
        sm[OFF_SQ +       tid] = g_sqn[f][rowI + tid];
        sm[OFF_SQ + 128 + tid] = g_sqn[f][rowJ + tid];
        sm[OFF_SQ + 256 + tid] = g_sqn[3 + f][rowI + tid];
        sm[OFF_SQ + 384 + tid] = g_sqn[3 + f][rowJ + tid];
    }

    // Global->smem staging slots: thread covers rows rA and rA+64 of each tile,
    // 4 consecutive k at qf*4.
    const int rA = tid >> 2;
    const int qf = tid & 3;
    const int sslot = (qf >> 1) * 8 + (qf & 1);   // slot base; elements at +0,2,4,6

    float s_total = 0.f;

#pragma unroll 1
    for (int phase = 0; phase < 2; ++phase) {
        const float* F  = phase ? T : P;
        const float* Ag = F + (size_t)rowI * D;
        const float* Bg = F + (size_t)rowJ * D;

        float acc[2][8][4];
#pragma unroll
        for (int mt = 0; mt < 2; mt++)
#pragma unroll
            for (int nt = 0; nt < 8; nt++)
#pragma unroll
                for (int e = 0; e < 4; e++) acc[mt][nt][e] = 0.f;

        // Prefetch chunk 0 and store to buffer 0.
        float4 va0 = *(const float4*)&Ag[(size_t)rA * D + qf * 4];
        float4 va1 = *(const float4*)&Ag[(size_t)(rA + 64) * D + qf * 4];
        float4 vb0 = *(const float4*)&Bg[(size_t)rA * D + qf * 4];
        float4 vb1 = *(const float4*)&Bg[(size_t)(rA + 64) * D + qf * 4];
        {
            uint32_t* tA = (uint32_t*)(sm + OFF_TILES);
            uint32_t* tB = (uint32_t*)(sm + OFF_TILES + TILE_F);
            int b0i = rA * PITCH + sslot, b1i = (rA + 64) * PITCH + sslot;
            tA[b0i] = to_tf32(va0.x); tA[b0i+2] = to_tf32(va0.y);
            tA[b0i+4] = to_tf32(va0.z); tA[b0i+6] = to_tf32(va0.w);
            tA[b1i] = to_tf32(va1.x); tA[b1i+2] = to_tf32(va1.y);
            tA[b1i+4] = to_tf32(va1.z); tA[b1i+6] = to_tf32(va1.w);
            tB[b0i] = to_tf32(vb0.x); tB[b0i+2] = to_tf32(vb0.y);
            tB[b0i+4] = to_tf32(vb0.z); tB[b0i+6] = to_tf32(vb0.w);
            tB[b1i] = to_tf32(vb1.x); tB[b1i+2] = to_tf32(vb1.y);
            tB[b1i+4] = to_tf32(vb1.z); tB[b1i+6] = to_tf32(vb1.w);
        }
        __syncthreads();

#pragma unroll 1
        for (int c = 0; c < D / BK; c++) {
            if (c < D / BK - 1) {
                const int k0 = (c + 1) * BK;
                va0 = *(const float4*)&Ag[(size_t)rA * D + k0 + qf * 4];
                va1 = *(const float4*)&Ag[(size_t)(rA + 64) * D + k0 + qf * 4];
                vb0 = *(const float4*)&Bg[(size_t)rA * D + k0 + qf * 4];
                vb1 = *(const float4*)&Bg[(size_t)(rA + 64) * D + k0 + qf * 4];
            }

            const float* sA = sm + OFF_TILES + (c & 1) * 2 * TILE_F;
            const float* sB = sA + TILE_F;
#pragma unroll
            for (int g = 0; g < 2; g++) {
                uint32_t a0[2], a1[2], a2[2], a3[2];
#pragma unroll
                for (int mt = 0; mt < 2; mt++) {
                    float2 lo = *(const float2*)&sA[(wi * 32 + mt * 16 + tg) * PITCH + g * 8 + 2 * q];
                    float2 hi = *(const float2*)&sA[(wi * 32 + mt * 16 + tg + 8) * PITCH + g * 8 + 2 * q];
                    a0[mt] = __float_as_uint(lo.x);
                    a2[mt] = __float_as_uint(lo.y);
                    a1[mt] = __float_as_uint(hi.x);
                    a3[mt] = __float_as_uint(hi.y);
                }
#pragma unroll
                for (int nt = 0; nt < 8; nt++) {
                    float2 fb = *(const float2*)&sB[(wj * 64 + nt * 8 + tg) * PITCH + g * 8 + 2 * q];
                    uint32_t b0 = __float_as_uint(fb.x), b1 = __float_as_uint(fb.y);
                    mma_tf32(acc[0][nt], a0[0], a1[0], a2[0], a3[0], b0, b1);
                    mma_tf32(acc[1][nt], a0[1], a1[1], a2[1], a3[1], b0, b1);
                }
            }

            if (c < D / BK - 1) {
                uint32_t* tA = (uint32_t*)(sm + OFF_TILES + ((c + 1) & 1) * 2 * TILE_F);
                uint32_t* tB = tA + TILE_F;
                int b0i = rA * PITCH + sslot, b1i = (rA + 64) * PITCH + sslot;
                tA[b0i] = to_tf32(va0.x); tA[b0i+2] = to_tf32(va0.y);
                tA[b0i+4] = to_tf32(va0.z); tA[b0i+6] = to_tf32(va0.w);
                tA[b1i] = to_tf32(va1.x); tA[b1i+2] = to_tf32(va1.y);
                tA[b1i+4] = to_tf32(va1.z); tA[b1i+6] = to_tf32(va1.w);
                tB[b0i] = to_tf32(vb0.x); tB[b0i+2] = to_tf32(vb0.y);
                tB[b0i+4] = to_tf32(vb0.z); tB[b0i+6] = to_tf32(vb0.w);
                tB[b1i] = to_tf32(vb1.x); tB[b1i+2] = to_tf32(vb1.y);
                tB[b1i+4] = to_tf32(vb1.z); tB[b1i+6] = to_tf32(vb1.w);
                __syncthreads();
            }
        }

        // Epilogue: distances; park dP (phase 0) or accumulate (phase 1).
        const float* sqi = sm + OFF_SQ + phase * 256;
        const float* sqj = sqi + 128;
#pragma unroll
        for (int mt = 0; mt < 2; mt++)
#pragma unroll
            for (int nt = 0; nt < 8; nt++)
#pragma unroll
                for (int e = 0; e < 4; e++) {
                    int lr = wi * 32 + mt * 16 + tg + ((e >> 1) << 3);
                    int lc = wj * 64 + nt * 8 + 2 * q + (e & 1);
                    float sq = sqi[lr] + sqj[lc] - 2.f * acc[mt][nt][e];
                    float dd = sq > 0.f ? sq * rsqrtf(sq) : 0.f;
                    int slot = OFF_SDP + ((mt * 8 + nt) * 4 + e) * 256 + tid;
                    if (phase == 0) {
                        sm[slot] = dd;
                    } else {
                        float d = sm[slot] - dd;
                        s_total += d * d;
                    }
                }
    }

    // Reduce with symmetry weight.
    s_total *= (bi == bj) ? 1.f : 2.f;
#pragma unroll
    for (int o = 16; o; o >>= 1) s_total += __shfl_xor_sync(0xffffffffu, s_total, o);
    if (lane == 0) sm[OFF_SRED + wid] = s_total;
    __syncthreads();
    if (tid == 0) {
        double tot = 0.0;
#pragma unroll
        for (int w = 0; w < 8; w++) tot += (double)sm[OFF_SRED + w];
        atomicAdd(&g_acc[1 + f], tot);
    }
}

// ---------------------------------------------------------------------------
__global__ void final_kernel(float* __restrict__ out) {
    double label = g_acc[0] / ((double)N * (double)C);
    double feat  = (g_acc[1] + g_acc[2] + g_acc[3]) / ((double)N * (double)N);
    out[0] = (float)((1.0 - 0.8) * label + 0.8 * feat / 3.0);
}

// ---------------------------------------------------------------------------
extern "C" void kernel_launch(void* const* d_in, const int* in_sizes, int n_in,
                              void* d_out, int out_size) {
    const float* pred   = (const float*)d_in[0];
    const float* target = (const float*)d_in[1];
    const float* pf0 = (const float*)d_in[2];
    const float* pf1 = (const float*)d_in[3];
    const float* pf2 = (const float*)d_in[4];
    const float* tf0 = (const float*)d_in[5];
    const float* tf1 = (const float*)d_in[6];
    const float* tf2 = (const float*)d_in[7];
    float* out = (float*)d_out;

    static int configured = 0;
    if (!configured) {
        cudaFuncSetAttribute(pair_kernel,
                             cudaFuncAttributeMaxDynamicSharedMemorySize, SMEM_BYTES);
        configured = 1;
    }

    zero_kernel<<<1, 32>>>();
    sqn_kernel<<<(6 * N) / 8, 256>>>(pf0, pf1, pf2, tf0, tf1, tf2);
    label_kernel<<<512, 256>>>(pred, target);

    dim3 grid(NTILES, 3);
    pair_kernel<<<grid, 256, SMEM_BYTES>>>(pf0, pf1, pf2, tf0, tf1, tf2);

    final_kernel<<<1, 1>>>(out);
}